// round 1
// baseline (speedup 1.0000x reference)
#include <cuda_runtime.h>
#include <cstddef>

// 2-layer LSTM (H=20) + FC head.
// B=4096 sequences, T=512 steps, input dim 1.
// 4 threads per sequence, each owning 5 hidden units of both layers.
// h-vectors exchanged via width-4 warp shuffles; weights resident in shared.

#define HID 20

__device__ __forceinline__ float sigm_f(float x) {
    // 1/(1+e^-x): MUFU.EX2 + MUFU.RCP, ~2^-22 rel err
    return __fdividef(1.0f, 1.0f + __expf(-x));
}
__device__ __forceinline__ float tanh_f(float x) {
    // 2*sigmoid(2x)-1
    return __fdividef(2.0f, 1.0f + __expf(-2.0f * x)) - 1.0f;
}

__global__ void __launch_bounds__(128, 1) lstm2_fc_kernel(
    const float* __restrict__ x,     // [B, T]
    const float* __restrict__ Wih0,  // [80, 1]
    const float* __restrict__ Whh0,  // [80, 20]
    const float* __restrict__ bih0,  // [80]
    const float* __restrict__ bhh0,  // [80]
    const float* __restrict__ Wih1,  // [80, 20]
    const float* __restrict__ Whh1,  // [80, 20]
    const float* __restrict__ bih1,  // [80]
    const float* __restrict__ bhh1,  // [80]
    const float* __restrict__ fcW,   // [1, 20]
    const float* __restrict__ fcb,   // [1]
    float* __restrict__ out,         // [B, 1]
    int Btot, int Tlen)
{
    __shared__ float sW0[80];        // Wih0 column (D==1)
    __shared__ float sB0[80];        // bih0 + bhh0
    __shared__ float sB1[80];        // bih1 + bhh1
    __shared__ float sWhh0[80 * 20];
    __shared__ float sWih1[80 * 20];
    __shared__ float sWhh1[80 * 20];
    __shared__ float sFc[20];
    __shared__ float sFcb;

    const int tid = threadIdx.x;
    for (int i = tid; i < 80; i += 128) {
        sW0[i] = Wih0[i];
        sB0[i] = bih0[i] + bhh0[i];
        sB1[i] = bih1[i] + bhh1[i];
    }
    for (int i = tid; i < 80 * 20; i += 128) {
        sWhh0[i] = Whh0[i];
        sWih1[i] = Wih1[i];
        sWhh1[i] = Whh1[i];
    }
    if (tid < 20) sFc[tid] = fcW[tid];
    if (tid == 0) sFcb = fcb[0];
    __syncthreads();

    // 4 consecutive lanes form a group handling one batch element.
    const int grp = tid >> 2;       // 0..31 within block
    const int sub = tid & 3;        // which 5-unit slice (0..3)
    int b = blockIdx.x * 32 + grp;
    const bool active = (b < Btot);
    if (b >= Btot) b = Btot - 1;    // keep all lanes running for shuffles

    const float* xb = x + (size_t)b * Tlen;

    // Per-thread state: 5 units of each layer.
    float h0[5], c0[5], h1[5], c1[5];
    #pragma unroll
    for (int i = 0; i < 5; ++i) { h0[i] = 0.f; c0[i] = 0.f; h1[i] = 0.f; c1[i] = 0.f; }

    // Loop-carried gathered vectors:
    // hh = full h0 of previous step (layer0 recurrent + layer1 input after refresh)
    // hb = full h1 of previous step (layer1 recurrent)
    float hh[20], hb[20];
    #pragma unroll
    for (int i = 0; i < 20; ++i) { hh[i] = 0.f; hb[i] = 0.f; }

    const unsigned FULL = 0xffffffffu;
    const int jbase = sub * 5;

    #pragma unroll 1
    for (int t = 0; t < Tlen; ++t) {
        const float xt = __ldg(&xb[t]);

        // ---------------- layer 0 ----------------
        #pragma unroll
        for (int jl = 0; jl < 5; ++jl) {
            const int j = jbase + jl;
            float gi = fmaf(sW0[j],      xt, sB0[j]);
            float gf = fmaf(sW0[20 + j], xt, sB0[20 + j]);
            float gg = fmaf(sW0[40 + j], xt, sB0[40 + j]);
            float go = fmaf(sW0[60 + j], xt, sB0[60 + j]);
            const float* wI = &sWhh0[(j)      * 20];
            const float* wF = &sWhh0[(20 + j) * 20];
            const float* wG = &sWhh0[(40 + j) * 20];
            const float* wO = &sWhh0[(60 + j) * 20];
            #pragma unroll
            for (int m = 0; m < 20; ++m) {
                const float hm = hh[m];
                gi = fmaf(wI[m], hm, gi);
                gf = fmaf(wF[m], hm, gf);
                gg = fmaf(wG[m], hm, gg);
                go = fmaf(wO[m], hm, go);
            }
            const float ai = sigm_f(gi);
            const float af = sigm_f(gf);
            const float ag = tanh_f(gg);
            const float ao = sigm_f(go);
            const float cn = fmaf(af, c0[jl], ai * ag);
            c0[jl] = cn;
            h0[jl] = ao * tanh_f(cn);
        }

        // Gather new full h0 across the 4-lane group (serves layer1 input now
        // and layer0 recurrence next step).
        #pragma unroll
        for (int mt = 0; mt < 4; ++mt)
            #pragma unroll
            for (int mi = 0; mi < 5; ++mi)
                hh[mt * 5 + mi] = __shfl_sync(FULL, h0[mi], mt, 4);

        // ---------------- layer 1 ----------------
        #pragma unroll
        for (int jl = 0; jl < 5; ++jl) {
            const int j = jbase + jl;
            float gi = sB1[j];
            float gf = sB1[20 + j];
            float gg = sB1[40 + j];
            float go = sB1[60 + j];
            const float* uI = &sWih1[(j)      * 20];
            const float* uF = &sWih1[(20 + j) * 20];
            const float* uG = &sWih1[(40 + j) * 20];
            const float* uO = &sWih1[(60 + j) * 20];
            const float* vI = &sWhh1[(j)      * 20];
            const float* vF = &sWhh1[(20 + j) * 20];
            const float* vG = &sWhh1[(40 + j) * 20];
            const float* vO = &sWhh1[(60 + j) * 20];
            #pragma unroll
            for (int m = 0; m < 20; ++m) {
                const float am = hh[m];
                const float bm = hb[m];
                gi = fmaf(uI[m], am, gi);
                gf = fmaf(uF[m], am, gf);
                gg = fmaf(uG[m], am, gg);
                go = fmaf(uO[m], am, go);
                gi = fmaf(vI[m], bm, gi);
                gf = fmaf(vF[m], bm, gf);
                gg = fmaf(vG[m], bm, gg);
                go = fmaf(vO[m], bm, go);
            }
            const float ai = sigm_f(gi);
            const float af = sigm_f(gf);
            const float ag = tanh_f(gg);
            const float ao = sigm_f(go);
            const float cn = fmaf(af, c1[jl], ai * ag);
            c1[jl] = cn;
            h1[jl] = ao * tanh_f(cn);
        }

        // Gather new full h1 for next step's recurrence.
        #pragma unroll
        for (int mt = 0; mt < 4; ++mt)
            #pragma unroll
            for (int mi = 0; mi < 5; ++mi)
                hb[mt * 5 + mi] = __shfl_sync(FULL, h1[mi], mt, 4);
    }

    // FC head: out[b] = fcW . h1_final + fcb  (group reduction)
    float p = 0.f;
    #pragma unroll
    for (int jl = 0; jl < 5; ++jl)
        p = fmaf(sFc[jbase + jl], h1[jl], p);
    p += __shfl_xor_sync(FULL, p, 1, 4);
    p += __shfl_xor_sync(FULL, p, 2, 4);
    if (active && sub == 0)
        out[b] = p + sFcb;
}

extern "C" void kernel_launch(void* const* d_in, const int* in_sizes, int n_in,
                              void* d_out, int out_size)
{
    const float* x    = (const float*)d_in[0];
    const float* Wih0 = (const float*)d_in[1];
    const float* Whh0 = (const float*)d_in[2];
    const float* bih0 = (const float*)d_in[3];
    const float* bhh0 = (const float*)d_in[4];
    const float* Wih1 = (const float*)d_in[5];
    const float* Whh1 = (const float*)d_in[6];
    const float* bih1 = (const float*)d_in[7];
    const float* bhh1 = (const float*)d_in[8];
    const float* fcW  = (const float*)d_in[9];
    const float* fcb  = (const float*)d_in[10];

    const int B = out_size;                 // out is [B, 1] fp32
    const int T = in_sizes[0] / B;          // x is [B, T, 1]
    const int blocks = (B + 31) / 32;       // 32 sequences per 128-thread block

    lstm2_fc_kernel<<<blocks, 128>>>(x, Wih0, Whh0, bih0, bhh0,
                                     Wih1, Whh1, bih1, bhh1,
                                     fcW, fcb, (float*)d_out, B, T);
}